// round 13
// baseline (speedup 1.0000x reference)
#include <cuda_runtime.h>

static constexpr int  B      = 256;
static constexpr int  H      = 512;
static constexpr long N_ELEM = 256L * 3 * 64 * 64;   // 3,145,728
static constexpr long N4     = N_ELEM / 4;           // 786,432 float4
static constexpr int  GRID   = 592;                  // 148 SMs * 4 CTAs: perfectly balanced wave
static constexpr int  TPB    = 256;
static constexpr int  IT_MAX = 6;                    // ceil(N4 / (GRID*TPB)) ; 6th iter predicated
static constexpr int  NWARP  = TPB / 32;             // 8

// Global accumulators: zero at module load; last block resets them every
// launch so each graph replay starts from zero.
__device__ float        g_acc_mse;
__device__ float        g_acc_pt;
__device__ unsigned int g_count;

__device__ __forceinline__ float warp_reduce_f(float v) {
    #pragma unroll
    for (int off = 16; off > 0; off >>= 1)
        v += __shfl_xor_sync(0xFFFFFFFFu, v, off);
    return v;
}

__global__ void __launch_bounds__(TPB)
fused_loss_kernel(const float4* __restrict__ y4,
                  const float4* __restrict__ x4,
                  const float2* __restrict__ z2,
                  float* __restrict__ out)
{
    const int tid  = threadIdx.x;
    const int lane = tid & 31;
    const int wid  = tid >> 5;
    const bool has_z = (blockIdx.x < B);

    __shared__ float s_mse[NWARP];
    __shared__ float s_s2[NWARP];
    __shared__ float s_s4[NWARP];

    const long base   = (long)blockIdx.x * TPB + tid;
    const long stride = (long)GRID * TPB;             // 151,552

    // z row: blocks 0..255, 2 floats/thread (256*2 = 512 = H)
    float2 zv = make_float2(0.f, 0.f);
    if (has_z) zv = z2[(long)blockIdx.x * (H / 2) + tid];

    // ---- MSE: 5 full iterations + 1 predicated, loads front-batched ----
    float4 ya[IT_MAX], xa[IT_MAX];
    #pragma unroll
    for (int k = 0; k < IT_MAX - 1; k++) ya[k] = y4[base + k * stride];
    #pragma unroll
    for (int k = 0; k < IT_MAX - 1; k++) xa[k] = x4[base + k * stride];

    const long idx5 = base + (long)(IT_MAX - 1) * stride;
    const bool tail = (idx5 < N4);
    ya[IT_MAX - 1] = tail ? y4[idx5] : make_float4(0.f, 0.f, 0.f, 0.f);
    xa[IT_MAX - 1] = tail ? x4[idx5] : make_float4(0.f, 0.f, 0.f, 0.f);

    float acc = 0.0f;
    #pragma unroll
    for (int k = 0; k < IT_MAX; k++) {
        float d0 = ya[k].x - xa[k].x;
        float d1 = ya[k].y - xa[k].y;
        float d2 = ya[k].z - xa[k].z;
        float d3 = ya[k].w - xa[k].w;
        acc += d0 * d0 + d1 * d1 + d2 * d2 + d3 * d3;
    }

    // ---- z math ----
    float q0 = zv.x * zv.x, q1 = zv.y * zv.y;
    float s2 = q0 + q1;
    float s4 = q0 * q0 + q1 * q1;

    acc = warp_reduce_f(acc);
    s2  = warp_reduce_f(s2);
    s4  = warp_reduce_f(s4);
    if (lane == 0) { s_mse[wid] = acc; s_s2[wid] = s2; s_s4[wid] = s4; }
    __syncthreads();

    // ---- thread 0: combine, RED, release-counter, (maybe) finalize ----
    if (tid == 0) {
        float m = 0.f, t2 = 0.f, t4 = 0.f;
        #pragma unroll
        for (int w = 0; w < NWARP; w++) { m += s_mse[w]; t2 += s_s2[w]; t4 += s_s4[w]; }

        atomicAdd(&g_acc_mse, m);                        // no-return -> REDG
        if (has_z) {
            double d2 = (double)t2;
            atomicAdd(&g_acc_pt, (float)(1.0 - (double)t4 / (d2 * d2)));
        }

        unsigned prev;
        asm volatile("atom.add.release.gpu.global.u32 %0, [%1], %2;"
                     : "=r"(prev) : "l"(&g_count), "r"(1u) : "memory");

        if (prev == (unsigned)(GRID - 1)) {
            float sum_sq = atomicAdd(&g_acc_mse, 0.0f);
            float sum_pt = atomicAdd(&g_acc_pt, 0.0f);

            double mse = (double)sum_sq / (double)N_ELEM;
            double pt  = (double)sum_pt / ((double)B * (double)H * (double)H);
            out[0] = (float)(mse + 0.1 * pt);

            g_acc_mse = 0.0f;
            g_acc_pt  = 0.0f;
            asm volatile("st.release.gpu.global.u32 [%0], %1;"
                         :: "l"(&g_count), "r"(0u) : "memory");
        }
    }
}

extern "C" void kernel_launch(void* const* d_in, const int* in_sizes, int n_in,
                              void* d_out, int out_size)
{
    const float4* y4 = (const float4*)d_in[0];   // yhat_xhat
    const float4* x4 = (const float4*)d_in[1];   // xhat
    const float2* z2 = (const float2*)d_in[2];   // z_xhat
    float* out = (float*)d_out;

    fused_loss_kernel<<<GRID, TPB>>>(y4, x4, z2, out);
}